// round 17
// baseline (speedup 1.0000x reference)
#include <cuda_runtime.h>

// Guided filter, fully fused, SMEM-free warp-sliding, 2 columns per lane,
// f32x2 packed math, TWO OUTPUT ROWS PER ITERATION.
// R16 config (CHUNKS=11 x CH=94, 128 thr, launch_bounds(128,8), 1188 blocks).
// Pair-step: vertical sums take 3 packed adds/quantity per 2 rows (vs 4),
// the two ABROWs are independent (rcp + shuffle latency overlap), loop and
// pointer overhead amortize over 2 outputs. Live state unchanged vs R16.

#define W 1024
#define H 1024
#define EPS81 8.1e-5f           // 81 * 1e-6
#define C9 (1.0f / 9.0f)

#define OUTC 60
#define BANDS 18                // ceil(1024/60)
#define CH 94                   // uniform chunk height (even)
#define CHUNKS 11
#define WPB 4                   // 128 threads
#define UNITS (24 * BANDS * CHUNKS)        // 4752 warps
#define NBLOCKS (UNITS / WPB)              // 1188 blocks

typedef unsigned long long ull;

__device__ __forceinline__ ull pk(float a, float b) {
    ull r; asm("mov.b64 %0, {%1, %2};" : "=l"(r) : "f"(a), "f"(b)); return r;
}
__device__ __forceinline__ void upk(ull v, float& a, float& b) {
    asm("mov.b64 {%0, %1}, %2;" : "=f"(a), "=f"(b) : "l"(v));
}
__device__ __forceinline__ ull addx(ull a, ull b) {
    ull r; asm("add.rn.f32x2 %0, %1, %2;" : "=l"(r) : "l"(a), "l"(b)); return r;
}
__device__ __forceinline__ ull mulx(ull a, ull b) {
    ull r; asm("mul.rn.f32x2 %0, %1, %2;" : "=l"(r) : "l"(a), "l"(b)); return r;
}
__device__ __forceinline__ ull fmax2p(ull a, ull b, ull c) {
    ull r; asm("fma.rn.f32x2 %0, %1, %2, %3;" : "=l"(r) : "l"(a), "l"(b), "l"(c)); return r;
}
__device__ __forceinline__ float rcpa(float v) {
    float r; asm("rcp.approx.f32 %0, %1;" : "=f"(r) : "f"(v)); return r;
}

__global__ __launch_bounds__(128, 8) void gf_kernel(const float* __restrict__ x,
                                                    const float* __restrict__ y,
                                                    float* __restrict__ out)
{
    const int wid  = threadIdx.x >> 5;
    const int lane = threadIdx.x & 31;
    const int g    = blockIdx.x * WPB + wid;

    const int plane = g / (BANDS * CHUNKS);
    const int rem   = g - plane * (BANDS * CHUNKS);
    const int band  = rem / CHUNKS;
    const int chunk = rem - band * CHUNKS;

    const int cfirst = band * OUTC - 2 + lane * 2;   // this lane's 2 columns
    const int cl     = min(max(cfirst, 0), W - 2);   // clamped aligned load col
    const int r0     = min(chunk * CH, H - CH);      // last chunk anchored at 930

    const bool dupL = (cfirst < 0);
    const bool dupR = (cfirst >= W);
    const bool pl   = (cfirst == 0);
    const bool pr   = (cfirst == W - 2);
    const bool do_store = (lane >= 1) && (lane <= 30) && (cfirst < W);

    const size_t pb = (size_t)plane * (size_t)(W * H);
    const float* __restrict__ px = x + pb + cl;
    const float* __restrict__ py = y + pb + cl;
    float* po = out + pb + (size_t)r0 * W + cfirst;

    const ull NINE2 = pk(9.0f, 9.0f);
    const ull NEG12 = pk(-1.0f, -1.0f);
    const ull EPS2  = pk(EPS81, EPS81);
    const ull C92   = pk(C9, C9);

#define LD2(v, P, row) { \
    v = *reinterpret_cast<const float2*>((P) + (size_t)(row) * W); \
    if (dupL) v.y = v.x; \
    if (dupR) v.x = v.y; }
#define LDP(v, PTR) { \
    v = *reinterpret_cast<const float2*>(PTR); \
    if (dupL) v.y = v.x; \
    if (dupR) v.x = v.y; }

    // Packed horizontal 3-sums (4 shuffles), outputs ull.
#define HQP(xv, yv, NX, NY, NXY, NXX) { \
    float xl = __shfl_up_sync(0xffffffffu, xv.y, 1); \
    float xr = __shfl_down_sync(0xffffffffu, xv.x, 1); \
    float yl = __shfl_up_sync(0xffffffffu, yv.y, 1); \
    float yr = __shfl_down_sync(0xffffffffu, yv.x, 1); \
    float mx = xv.x + xv.y, my = yv.x + yv.y; \
    float mxy = fmaf(xv.x, yv.x, xv.y * yv.y); \
    float mxx = fmaf(xv.x, xv.x, xv.y * xv.y); \
    NX  = pk(xl + mx, mx + xr); \
    NY  = pk(yl + my, my + yr); \
    NXY = pk(fmaf(xl, yl, mxy), fmaf(xr, yr, mxy)); \
    NXX = pk(fmaf(xl, xl, mxx), fmaf(xr, xr, mxx)); }

    // Packed A,b9 + horizontal 3-sum with column replication (4 shuffles).
#define ABP(Sxp, Syp, Sxyp, Sxxp, HA, HB) { \
    ull t9  = mulx(Sxyp, NINE2); \
    ull nSy = mulx(Syp, NEG12); \
    ull num = fmax2p(Sxp, nSy, t9); \
    ull nSx = mulx(Sxp, NEG12); \
    ull uu  = fmax2p(nSx, Sxp, EPS2); \
    ull den = fmax2p(Sxxp, NINE2, uu); \
    float d0, d1; upk(den, d0, d1); \
    ull rcp2 = pk(rcpa(d0), rcpa(d1)); \
    ull Ap = mulx(num, rcp2); \
    ull Bp = fmax2p(Ap, nSx, Syp); \
    float a0, a1, b0, b1; \
    upk(Ap, a0, a1);  upk(Bp, b0, b1); \
    float Al = __shfl_up_sync(0xffffffffu, a1, 1); \
    float Ar = __shfl_down_sync(0xffffffffu, a0, 1); \
    float Bl = __shfl_up_sync(0xffffffffu, b1, 1); \
    float Br = __shfl_down_sync(0xffffffffu, b0, 1); \
    if (pl) { Al = a0;  Bl = b0; } \
    if (pr) { Ar = a1;  Br = b1; } \
    float ma = a0 + a1, mb = b0 + b1; \
    HA = pk(Al + ma, ma + Ar); \
    HB = pk(Bl + mb, mb + Br); }

    // Emit one output row from packed sums.
#define EMIT(SAp, SBp, XCP, POFF) { \
    ull sbc = mulx(SBp, C92); \
    ull rp  = mulx(fmax2p(SAp, XCP, sbc), C92); \
    float r0f, r1f; upk(rp, r0f, r1f); \
    r0f = fminf(fmaxf(truncf(r0f), 0.0f), 255.0f); \
    r1f = fminf(fmaxf(truncf(r1f), 0.0f), 255.0f); \
    if (do_store) *reinterpret_cast<float2*>(po + (POFF)) = make_float2(r0f, r1f); }

    // Packed sliding-sum state (invariant at top of step for output row rr):
    //   hp* = h at input row rr+1,  P* = h[rr] + h[rr+1]
    //   hApp = hA at A-row rr,      PAp = hA[rr-1] + hA[rr]  (B likewise)
    //   xc0p = x[rr], xc1p = x[rr+1]
    ull hpxp, hpyp, hpxyp, hpxxp, Pxp, Pyp, Pxyp, Pxxp;
    ull hApp, hBpp, PAp, PBp;
    ull xc0p, xc1p;

    // ---------------- prologue (scalar-ish, pack at the end) ----------------
    {
        ull t0x, t0y, t0xy, t0xx, t1x, t1y, t1xy, t1xx;
        ull h0x, h0y, h0xy, h0xx, h1x, h1y, h1xy, h1xx;
        float2 xv, yv;
        LD2(xv, px, max(r0 - 2, 0))  LD2(yv, py, max(r0 - 2, 0))
        HQP(xv, yv, t0x, t0y, t0xy, t0xx)
        LD2(xv, px, max(r0 - 1, 0))  LD2(yv, py, max(r0 - 1, 0))
        HQP(xv, yv, t1x, t1y, t1xy, t1xx)
        LD2(xv, px, r0)              LD2(yv, py, r0)
        HQP(xv, yv, h0x, h0y, h0xy, h0xx)
        xc0p = pk(xv.x, xv.y);
        LD2(xv, px, r0 + 1)          LD2(yv, py, r0 + 1)
        HQP(xv, yv, h1x, h1y, h1xy, h1xx)
        xc1p = pk(xv.x, xv.y);

        ull hAm, hBm, hA0, hB0;
        ABP(addx(addx(t0x, t1x), h0x), addx(addx(t0y, t1y), h0y),
            addx(addx(t0xy, t1xy), h0xy), addx(addx(t0xx, t1xx), h0xx),
            hAm, hBm)                                        // A row r0-1
        ABP(addx(addx(t1x, h0x), h1x), addx(addx(t1y, h0y), h1y),
            addx(addx(t1xy, h0xy), h1xy), addx(addx(t1xx, h0xx), h1xx),
            hA0, hB0)                                        // A row r0
        if (r0 == 0) { hAm = hA0;  hBm = hB0; }              // top: A(-1):=A(0)

        hpxp  = h1x;   hpyp  = h1y;   hpxyp = h1xy;  hpxxp = h1xx;
        Pxp  = addx(h0x, h1x);   Pyp  = addx(h0y, h1y);
        Pxyp = addx(h0xy, h1xy); Pxxp = addx(h0xx, h1xx);
        hApp = hA0;  hBpp = hB0;
        PAp  = addx(hAm, hA0);   PBp = addx(hBm, hB0);
    }

    // Prefetched input rows r0+2, r0+3; pxr/pyr point at r0+4.
    float2 pxa, pya, pxb, pyb;
    LD2(pxa, px, r0 + 2)  LD2(pya, py, r0 + 2)
    LD2(pxb, px, r0 + 3)  LD2(pyb, py, r0 + 3)
    const float* pxr = px + (size_t)(r0 + 4) * W;
    const float* pyr = py + (size_t)(r0 + 4) * W;

    // -------- pair loop: 45 iterations, outputs r0 .. r0+89 --------
    // Iteration i consumes input rows r0+2i+2, r0+2i+3 and prefetches the next
    // two; max row loaded = r0+93 <= 1023 for every chunk (r0 <= 930).
#pragma unroll 3
    for (int i = 0; i < (CH - 4) / 2; ++i) {
        float2 xa = pxa, ya = pya, xb = pxb, yb = pyb;
        LDP(pxa, pxr)      LDP(pya, pyr)
        LDP(pxb, pxr + W)  LDP(pyb, pyr + W)
        pxr += 2 * W;  pyr += 2 * W;

        ull n1x, n1y, n1xy, n1xx, n2x, n2y, n2xy, n2xx;
        HQP(xa, ya, n1x, n1y, n1xy, n1xx)
        HQP(xb, yb, n2x, n2y, n2xy, n2xx)

        ull S1x = addx(Pxp, n1x);   ull tx = addx(n1x, n2x);
        ull S2x = addx(hpxp, tx);   Pxp = tx;   hpxp = n2x;
        ull S1y = addx(Pyp, n1y);   ull ty = addx(n1y, n2y);
        ull S2y = addx(hpyp, ty);   Pyp = ty;   hpyp = n2y;
        ull S1xy = addx(Pxyp, n1xy); ull txy = addx(n1xy, n2xy);
        ull S2xy = addx(hpxyp, txy); Pxyp = txy; hpxyp = n2xy;
        ull S1xx = addx(Pxxp, n1xx); ull txx = addx(n1xx, n2xx);
        ull S2xx = addx(hpxxp, txx); Pxxp = txx; hpxxp = n2xx;

        ull hA1, hB1, hA2, hB2;
        ABP(S1x, S1y, S1xy, S1xx, hA1, hB1)    // A row rr+1
        ABP(S2x, S2y, S2xy, S2xx, hA2, hB2)    // A row rr+2 (independent)

        ull SA1 = addx(PAp, hA1);  ull tA = addx(hA1, hA2);
        ull SA2 = addx(hApp, tA);  PAp = tA;  hApp = hA2;
        ull SB1 = addx(PBp, hB1);  ull tB = addx(hB1, hB2);
        ull SB2 = addx(hBpp, tB);  PBp = tB;  hBpp = hB2;

        EMIT(SA1, SB1, xc0p, 0)
        EMIT(SA2, SB2, xc1p, W)
        po += 2 * W;
        xc0p = pk(xa.x, xa.y);
        xc1p = pk(xb.x, xb.y);
    }

    // -------- guarded tail: 4 single steps, outputs r0+90 .. r0+93 --------
    // Input rows r0+92, r0+93 are in the prefetch registers; rows r0+94/95
    // are loaded clamped (row replication for the last chunk).
#define STEPT(k, XV, YV) { \
        const int rr = r0 + (CH - 4) + (k); \
        ull nx, ny, nxy, nxx; \
        HQP(XV, YV, nx, ny, nxy, nxx) \
        ull Sx = addx(Pxp, nx);   Pxp = addx(hpxp, nx);    hpxp = nx; \
        ull Sy = addx(Pyp, ny);   Pyp = addx(hpyp, ny);    hpyp = ny; \
        ull Sxy = addx(Pxyp, nxy); Pxyp = addx(hpxyp, nxy); hpxyp = nxy; \
        ull Sxx = addx(Pxxp, nxx); Pxxp = addx(hpxxp, nxx); hpxxp = nxx; \
        ull hAn, hBn; \
        ABP(Sx, Sy, Sxy, Sxx, hAn, hBn) \
        if (rr + 1 >= H) { hAn = hApp;  hBn = hBpp; }   /* A(H) := A(H-1) */ \
        ull SA = addx(PAp, hAn);  PAp = addx(hApp, hAn);  hApp = hAn; \
        ull SB = addx(PBp, hBn);  PBp = addx(hBpp, hBn);  hBpp = hBn; \
        EMIT(SA, SB, xc0p, 0) \
        po += W; \
        xc0p = xc1p;  xc1p = pk(XV.x, XV.y); }

    STEPT(0, pxa, pya)
    STEPT(1, pxb, pyb)
    {
        float2 xv, yv;
        LD2(xv, px, min(r0 + CH, H - 1))  LD2(yv, py, min(r0 + CH, H - 1))
        STEPT(2, xv, yv)
    }
    {
        float2 xv, yv;
        LD2(xv, px, min(r0 + CH + 1, H - 1))  LD2(yv, py, min(r0 + CH + 1, H - 1))
        STEPT(3, xv, yv)
    }
#undef STEPT
#undef EMIT
#undef ABP
#undef HQP
#undef LDP
#undef LD2
}

extern "C" void kernel_launch(void* const* d_in, const int* in_sizes, int n_in,
                              void* d_out, int out_size) {
    const float* x = (const float*)d_in[0];
    const float* y = (const float*)d_in[1];
    float* out     = (float*)d_out;

    gf_kernel<<<NBLOCKS, 32 * WPB>>>(x, y, out);
}